// round 8
// baseline (speedup 1.0000x reference)
#include <cuda_runtime.h>
#include <cstdint>
#include <math.h>

// Problem constants (B=2, S=2048, D=2048, H=16, hd=128)
#define B_    2
#define S_    2048
#define D_    2048
#define H_    16
#define HD_   128
#define MTOK  (B_ * S_)   // 4096 token rows

// ---------------- scratch (static device globals; no allocation) -------------
__device__ float g_q[(size_t)B_ * S_ * D_];
__device__ float g_k[(size_t)B_ * S_ * D_];
__device__ float g_v[(size_t)B_ * S_ * D_];
__device__ float g_ctx[(size_t)B_ * S_ * D_];

// ---------------- tf32 helpers ----------------------------------------------
__device__ __forceinline__ uint32_t f2tf32(float f) {
    uint32_t r;
    asm("cvt.rna.tf32.f32 %0, %1;" : "=r"(r) : "f"(f));
    return r;
}
__device__ __forceinline__ uint4 tf32x4(float4 v) {
    uint4 u;
    u.x = f2tf32(v.x); u.y = f2tf32(v.y); u.z = f2tf32(v.z); u.w = f2tf32(v.w);
    return u;
}
// D += A(16x8) * B(8x8), tf32 in, fp32 accum. Standard m16n8k8 fragment layout.
__device__ __forceinline__ void mma_tf32(float* d, const uint32_t* a, const uint32_t* b) {
    asm volatile(
        "mma.sync.aligned.m16n8k8.row.col.f32.tf32.tf32.f32 "
        "{%0,%1,%2,%3}, {%4,%5,%6,%7}, {%8,%9}, {%0,%1,%2,%3};\n"
        : "+f"(d[0]), "+f"(d[1]), "+f"(d[2]), "+f"(d[3])
        : "r"(a[0]), "r"(a[1]), "r"(a[2]), "r"(a[3]), "r"(b[0]), "r"(b[1]));
}

// ============================================================================
// GEMM: Y[M,N] = A[M,K] @ W[N,K]^T   (W row-major [N,K] == col-major B operand)
// Block tile 128x128, BK=32, 256 threads (8 warps, 4x2), warp tile 32x64.
// M = MTOK (4096), N = K = D_ (2048), all hardcoded.
// ============================================================================
#define GBM 128
#define GBN 128
#define GBK 32
#define GSK 36   // smem row stride (36 % 32 == 4 -> frag LDS bank = 4g+t, conflict-free)

__global__ __launch_bounds__(256) void gemm_xwt_tf32(
    const float* __restrict__ A, const float* __restrict__ W, float* __restrict__ Y)
{
    __shared__ uint32_t As[GBM * GSK];
    __shared__ uint32_t Bs[GBN * GSK];
    const int K = D_, N = D_;

    const int tid  = threadIdx.x;
    const int lane = tid & 31;
    const int warp = tid >> 5;
    const int g = lane >> 2, t = lane & 3;
    const int wm = warp & 3;        // 0..3 -> 32-row slab
    const int wn = warp >> 2;       // 0..1 -> 64-col slab
    const int bm0 = blockIdx.y * GBM;
    const int bn0 = blockIdx.x * GBN;

    float acc[2][8][4];
#pragma unroll
    for (int mi = 0; mi < 2; mi++)
#pragma unroll
        for (int ni = 0; ni < 8; ni++)
#pragma unroll
            for (int j = 0; j < 4; j++) acc[mi][ni][j] = 0.f;

    for (int k0 = 0; k0 < K; k0 += GBK) {
        // Load+convert tiles: 1024 float4 per tile, 4 per thread per tile.
#pragma unroll
        for (int i = 0; i < 4; i++) {
            int idx = tid + i * 256;          // 0..1023
            int r = idx >> 3;                 // row 0..127
            int c = (idx & 7) << 2;           // col 0..28 step 4
            float4 va = *(const float4*)(A + (size_t)(bm0 + r) * K + k0 + c);
            float4 vb = *(const float4*)(W + (size_t)(bn0 + r) * K + k0 + c);
            *(uint4*)&As[r * GSK + c] = tf32x4(va);
            *(uint4*)&Bs[r * GSK + c] = tf32x4(vb);
        }
        __syncthreads();

#pragma unroll
        for (int ks = 0; ks < GBK; ks += 8) {
            uint32_t af[2][4], bf[8][2];
#pragma unroll
            for (int mi = 0; mi < 2; mi++) {
                int r0 = wm * 32 + mi * 16;
                af[mi][0] = As[(r0 + g    ) * GSK + ks + t    ];
                af[mi][1] = As[(r0 + g + 8) * GSK + ks + t    ];
                af[mi][2] = As[(r0 + g    ) * GSK + ks + t + 4];
                af[mi][3] = As[(r0 + g + 8) * GSK + ks + t + 4];
            }
#pragma unroll
            for (int ni = 0; ni < 8; ni++) {
                int c0 = wn * 64 + ni * 8;
                bf[ni][0] = Bs[(c0 + g) * GSK + ks + t    ];
                bf[ni][1] = Bs[(c0 + g) * GSK + ks + t + 4];
            }
#pragma unroll
            for (int mi = 0; mi < 2; mi++)
#pragma unroll
                for (int ni = 0; ni < 8; ni++)
                    mma_tf32(acc[mi][ni], af[mi], bf[ni]);
        }
        __syncthreads();
    }

#pragma unroll
    for (int mi = 0; mi < 2; mi++)
#pragma unroll
        for (int ni = 0; ni < 8; ni++) {
            int r0 = bm0 + wm * 32 + mi * 16 + g;
            int c0 = bn0 + wn * 64 + ni * 8 + 2 * t;
            *(float2*)&Y[(size_t)r0 * N + c0] =
                make_float2(acc[mi][ni][0], acc[mi][ni][1]);
            *(float2*)&Y[(size_t)(r0 + 8) * N + c0] =
                make_float2(acc[mi][ni][2], acc[mi][ni][3]);
        }
}

// ============================================================================
// Flash attention: per block = (q-tile of 128 rows, head h, batch b).
// 8 warps, each owns 16 q-rows (full-row softmax within a warp/quad).
// KV tile = 64. All smem tiles are tf32; strides chosen for conflict-free
// fragment LDS:  Q/K stride 132 (=4 mod 32, bank 4g+t),
//                V  stride 136 (=8 mod 32, bank 8t+g; V read directly as B op,
//                               no transpose needed),
//                P  stride 68  (=4 mod 32).
// ============================================================================
#define FQ   128
#define FKV  64
#define SQW  132
#define SVW  136
#define SPW  68
#define QOFF 0
#define KOFF (FQ * SQW)                 // 16896
#define VOFF (KOFF + FKV * SQW)         // 25344
#define POFF (VOFF + FKV * SVW)         // 34048
#define FSMEM_WORDS (POFF + FQ * SPW)   // 42752
#define FSMEM_BYTES (FSMEM_WORDS * 4)   // 171008 B

__global__ __launch_bounds__(256) void flash_tf32(
    const float* __restrict__ Q, const float* __restrict__ Kg,
    const float* __restrict__ Vg, float* __restrict__ O)
{
    extern __shared__ uint32_t sm[];
    const int tid  = threadIdx.x;
    const int lane = tid & 31;
    const int w    = tid >> 5;
    const int g = lane >> 2, t = lane & 3;
    const int qt = blockIdx.x, h = blockIdx.y, b = blockIdx.z;
    const int wr = w * 16;

    const size_t qbase  = ((size_t)(b * S_ + qt * FQ)) * D_ + (size_t)h * HD_;
    const size_t kvbase = ((size_t)b * S_) * D_ + (size_t)h * HD_;

    // Load Q tile [128,128] -> smem tf32 (resident for whole kernel)
#pragma unroll
    for (int i = 0; i < 16; i++) {
        int idx = tid + i * 256;          // 0..4095 float4 slots
        int r = idx >> 5;                 // 0..127
        int c = (idx & 31) << 2;          // 0..124
        float4 v = *(const float4*)(Q + qbase + (size_t)r * D_ + c);
        *(uint4*)&sm[QOFF + r * SQW + c] = tf32x4(v);
    }

    float o[16][4];
#pragma unroll
    for (int ni = 0; ni < 16; ni++)
#pragma unroll
        for (int j = 0; j < 4; j++) o[ni][j] = 0.f;
    float m0 = -1e30f, m1 = -1e30f, l0 = 0.f, l1 = 0.f;
    const float scale = 0.08838834764831845f;   // 1/sqrt(128)

    for (int kv0 = 0; kv0 < S_; kv0 += FKV) {
        // Load K and V tiles [64,128] (V kept [kv,d] — read directly as B op)
#pragma unroll
        for (int i = 0; i < 8; i++) {
            int idx = tid + i * 256;      // 0..2047 float4 slots
            int r = idx >> 5;             // 0..63
            int c = (idx & 31) << 2;      // 0..124
            size_t goff = kvbase + (size_t)(kv0 + r) * D_ + c;
            *(uint4*)&sm[KOFF + r * SQW + c] = tf32x4(*(const float4*)(Kg + goff));
            *(uint4*)&sm[VOFF + r * SVW + c] = tf32x4(*(const float4*)(Vg + goff));
        }
        __syncthreads();

        // ---- S = Q @ K^T  (M=16 per warp, N=64, K=128) ----
        float s[8][4];
#pragma unroll
        for (int ni = 0; ni < 8; ni++)
#pragma unroll
            for (int j = 0; j < 4; j++) s[ni][j] = 0.f;

#pragma unroll
        for (int ks = 0; ks < HD_; ks += 8) {
            uint32_t af[4];
            af[0] = sm[QOFF + (wr + g    ) * SQW + ks + t    ];
            af[1] = sm[QOFF + (wr + g + 8) * SQW + ks + t    ];
            af[2] = sm[QOFF + (wr + g    ) * SQW + ks + t + 4];
            af[3] = sm[QOFF + (wr + g + 8) * SQW + ks + t + 4];
#pragma unroll
            for (int ni = 0; ni < 8; ni++) {
                uint32_t bf[2];
                bf[0] = sm[KOFF + (ni * 8 + g) * SQW + ks + t    ];
                bf[1] = sm[KOFF + (ni * 8 + g) * SQW + ks + t + 4];
                mma_tf32(s[ni], af, bf);
            }
        }

        // ---- online softmax (rows g and g+8 within the quad) ----
        float mx0 = -1e30f, mx1 = -1e30f;
#pragma unroll
        for (int ni = 0; ni < 8; ni++) {
#pragma unroll
            for (int j = 0; j < 4; j++) s[ni][j] *= scale;
            mx0 = fmaxf(mx0, fmaxf(s[ni][0], s[ni][1]));
            mx1 = fmaxf(mx1, fmaxf(s[ni][2], s[ni][3]));
        }
        mx0 = fmaxf(mx0, __shfl_xor_sync(0xffffffffu, mx0, 1));
        mx0 = fmaxf(mx0, __shfl_xor_sync(0xffffffffu, mx0, 2));
        mx1 = fmaxf(mx1, __shfl_xor_sync(0xffffffffu, mx1, 1));
        mx1 = fmaxf(mx1, __shfl_xor_sync(0xffffffffu, mx1, 2));
        float mn0 = fmaxf(m0, mx0), mn1 = fmaxf(m1, mx1);
        float a0 = __expf(m0 - mn0), a1 = __expf(m1 - mn1);
        m0 = mn0; m1 = mn1;

        float r0 = 0.f, r1 = 0.f;
#pragma unroll
        for (int ni = 0; ni < 8; ni++) {
            float p0 = __expf(s[ni][0] - mn0);
            float p1 = __expf(s[ni][1] - mn0);
            float p2 = __expf(s[ni][2] - mn1);
            float p3 = __expf(s[ni][3] - mn1);
            r0 += p0 + p1; r1 += p2 + p3;
            uint2 u01 = make_uint2(f2tf32(p0), f2tf32(p1));
            uint2 u23 = make_uint2(f2tf32(p2), f2tf32(p3));
            *(uint2*)&sm[POFF + (wr + g    ) * SPW + ni * 8 + 2 * t] = u01;
            *(uint2*)&sm[POFF + (wr + g + 8) * SPW + ni * 8 + 2 * t] = u23;
        }
        r0 += __shfl_xor_sync(0xffffffffu, r0, 1);
        r0 += __shfl_xor_sync(0xffffffffu, r0, 2);
        r1 += __shfl_xor_sync(0xffffffffu, r1, 1);
        r1 += __shfl_xor_sync(0xffffffffu, r1, 2);
        l0 = l0 * a0 + r0;
        l1 = l1 * a1 + r1;
#pragma unroll
        for (int ni = 0; ni < 16; ni++) {
            o[ni][0] *= a0; o[ni][1] *= a0; o[ni][2] *= a1; o[ni][3] *= a1;
        }
        __syncwarp();   // P stores visible to this warp's PV loads (region is warp-private)

        // ---- O += P @ V  (M=16, N=128, K=64) ----
#pragma unroll
        for (int ks = 0; ks < FKV; ks += 8) {
            uint32_t af[4];
            af[0] = sm[POFF + (wr + g    ) * SPW + ks + t    ];
            af[1] = sm[POFF + (wr + g + 8) * SPW + ks + t    ];
            af[2] = sm[POFF + (wr + g    ) * SPW + ks + t + 4];
            af[3] = sm[POFF + (wr + g + 8) * SPW + ks + t + 4];
#pragma unroll
            for (int ni = 0; ni < 16; ni++) {
                uint32_t bf[2];
                bf[0] = sm[VOFF + (ks + t    ) * SVW + ni * 8 + g];
                bf[1] = sm[VOFF + (ks + t + 4) * SVW + ni * 8 + g];
                mma_tf32(o[ni], af, bf);
            }
        }
        __syncthreads();   // protect K/V/P tiles before next iteration's overwrites
    }

    // ---- epilogue: normalize, write ctx ----
    float i0 = 1.0f / l0;
    float i1 = 1.0f / l1;
#pragma unroll
    for (int ni = 0; ni < 16; ni++) {
        int c0 = ni * 8 + 2 * t;
        *(float2*)&O[qbase + (size_t)(wr + g) * D_ + c0] =
            make_float2(o[ni][0] * i0, o[ni][1] * i0);
        *(float2*)&O[qbase + (size_t)(wr + g + 8) * D_ + c0] =
            make_float2(o[ni][2] * i1, o[ni][3] * i1);
    }
}

// ============================================================================
// Launch: q=x@wq^T, k=x@wk^T, v=x@wv^T, flash attention, out=ctx@wo^T
// ============================================================================
extern "C" void kernel_launch(void* const* d_in, const int* in_sizes, int n_in,
                              void* d_out, int out_size) {
    const float* x  = (const float*)d_in[0];
    const float* wq = (const float*)d_in[1];
    const float* wk = (const float*)d_in[2];
    const float* wv = (const float*)d_in[3];
    const float* wo = (const float*)d_in[4];
    float* out = (float*)d_out;

    float *qb, *kb, *vb, *cb;
    cudaGetSymbolAddress((void**)&qb, g_q);
    cudaGetSymbolAddress((void**)&kb, g_k);
    cudaGetSymbolAddress((void**)&vb, g_v);
    cudaGetSymbolAddress((void**)&cb, g_ctx);

    cudaFuncSetAttribute(flash_tf32,
                         cudaFuncAttributeMaxDynamicSharedMemorySize, FSMEM_BYTES);

    dim3 gg(D_ / GBN, MTOK / GBM);   // (16, 32)
    gemm_xwt_tf32<<<gg, 256>>>(x, wq, qb);
    gemm_xwt_tf32<<<gg, 256>>>(x, wk, kb);
    gemm_xwt_tf32<<<gg, 256>>>(x, wv, vb);
    flash_tf32<<<dim3(S_ / FQ, H_, B_), 256, FSMEM_BYTES>>>(qb, kb, vb, cb);
    gemm_xwt_tf32<<<gg, 256>>>(cb, wo, out);
}

// round 9
// speedup vs baseline: 1.0130x; 1.0130x over previous
#include <cuda_runtime.h>
#include <cstdint>
#include <math.h>

// Problem constants (B=2, S=2048, D=2048, H=16, hd=128)
#define B_    2
#define S_    2048
#define D_    2048
#define H_    16
#define HD_   128
#define MTOK  (B_ * S_)   // 4096 token rows

// ---------------- scratch (static device globals; no allocation) -------------
__device__ float g_q[(size_t)B_ * S_ * D_];
__device__ float g_k[(size_t)B_ * S_ * D_];
__device__ float g_v[(size_t)B_ * S_ * D_];
__device__ float g_ctx[(size_t)B_ * S_ * D_];

// ---------------- tf32 helpers ----------------------------------------------
__device__ __forceinline__ uint32_t f2tf32(float f) {
    uint32_t r;
    asm("cvt.rna.tf32.f32 %0, %1;" : "=r"(r) : "f"(f));
    return r;
}
__device__ __forceinline__ uint4 tf32x4(float4 v) {
    uint4 u;
    u.x = f2tf32(v.x); u.y = f2tf32(v.y); u.z = f2tf32(v.z); u.w = f2tf32(v.w);
    return u;
}
// D += A(16x8) * B(8x8), tf32 in, fp32 accum. Standard m16n8k8 fragment layout.
__device__ __forceinline__ void mma_tf32(float* d, const uint32_t* a, const uint32_t* b) {
    asm volatile(
        "mma.sync.aligned.m16n8k8.row.col.f32.tf32.tf32.f32 "
        "{%0,%1,%2,%3}, {%4,%5,%6,%7}, {%8,%9}, {%0,%1,%2,%3};\n"
        : "+f"(d[0]), "+f"(d[1]), "+f"(d[2]), "+f"(d[3])
        : "r"(a[0]), "r"(a[1]), "r"(a[2]), "r"(a[3]), "r"(b[0]), "r"(b[1]));
}

// ============================================================================
// GEMM: Y[M,N] = A[M,K] @ W[N,K]^T   (W row-major [N,K] == col-major B operand)
// Block tile 128x128, BK=32, 256 threads (8 warps, 4x2), warp tile 32x64.
// M = MTOK (4096), N = K = D_ (2048), all hardcoded.
// ============================================================================
#define GBM 128
#define GBN 128
#define GBK 32
#define GSK 36   // smem row stride (36 % 32 == 4 -> frag LDS bank = 4g+t, conflict-free)

__global__ __launch_bounds__(256) void gemm_xwt_tf32(
    const float* __restrict__ A, const float* __restrict__ W, float* __restrict__ Y)
{
    __shared__ uint32_t As[GBM * GSK];
    __shared__ uint32_t Bs[GBN * GSK];
    const int K = D_, N = D_;

    const int tid  = threadIdx.x;
    const int lane = tid & 31;
    const int warp = tid >> 5;
    const int g = lane >> 2, t = lane & 3;
    const int wm = warp & 3;        // 0..3 -> 32-row slab
    const int wn = warp >> 2;       // 0..1 -> 64-col slab
    const int bm0 = blockIdx.y * GBM;
    const int bn0 = blockIdx.x * GBN;

    float acc[2][8][4];
#pragma unroll
    for (int mi = 0; mi < 2; mi++)
#pragma unroll
        for (int ni = 0; ni < 8; ni++)
#pragma unroll
            for (int j = 0; j < 4; j++) acc[mi][ni][j] = 0.f;

    for (int k0 = 0; k0 < K; k0 += GBK) {
        // Load+convert tiles: 1024 float4 per tile, 4 per thread per tile.
#pragma unroll
        for (int i = 0; i < 4; i++) {
            int idx = tid + i * 256;          // 0..1023
            int r = idx >> 3;                 // row 0..127
            int c = (idx & 7) << 2;           // col 0..28 step 4
            float4 va = *(const float4*)(A + (size_t)(bm0 + r) * K + k0 + c);
            float4 vb = *(const float4*)(W + (size_t)(bn0 + r) * K + k0 + c);
            *(uint4*)&As[r * GSK + c] = tf32x4(va);
            *(uint4*)&Bs[r * GSK + c] = tf32x4(vb);
        }
        __syncthreads();

#pragma unroll
        for (int ks = 0; ks < GBK; ks += 8) {
            uint32_t af[2][4], bf[8][2];
#pragma unroll
            for (int mi = 0; mi < 2; mi++) {
                int r0 = wm * 32 + mi * 16;
                af[mi][0] = As[(r0 + g    ) * GSK + ks + t    ];
                af[mi][1] = As[(r0 + g + 8) * GSK + ks + t    ];
                af[mi][2] = As[(r0 + g    ) * GSK + ks + t + 4];
                af[mi][3] = As[(r0 + g + 8) * GSK + ks + t + 4];
            }
#pragma unroll
            for (int ni = 0; ni < 8; ni++) {
                int c0 = wn * 64 + ni * 8;
                bf[ni][0] = Bs[(c0 + g) * GSK + ks + t    ];
                bf[ni][1] = Bs[(c0 + g) * GSK + ks + t + 4];
            }
#pragma unroll
            for (int mi = 0; mi < 2; mi++)
#pragma unroll
                for (int ni = 0; ni < 8; ni++)
                    mma_tf32(acc[mi][ni], af[mi], bf[ni]);
        }
        __syncthreads();
    }

#pragma unroll
    for (int mi = 0; mi < 2; mi++)
#pragma unroll
        for (int ni = 0; ni < 8; ni++) {
            int r0 = bm0 + wm * 32 + mi * 16 + g;
            int c0 = bn0 + wn * 64 + ni * 8 + 2 * t;
            *(float2*)&Y[(size_t)r0 * N + c0] =
                make_float2(acc[mi][ni][0], acc[mi][ni][1]);
            *(float2*)&Y[(size_t)(r0 + 8) * N + c0] =
                make_float2(acc[mi][ni][2], acc[mi][ni][3]);
        }
}

// ============================================================================
// Flash attention: per block = (q-tile of 128 rows, head h, batch b).
// 8 warps, each owns 16 q-rows (full-row softmax within a warp/quad).
// KV tile = 64. All smem tiles are tf32; strides chosen for conflict-free
// fragment LDS:  Q/K stride 132 (=4 mod 32, bank 4g+t),
//                V  stride 136 (=8 mod 32, bank 8t+g; V read directly as B op,
//                               no transpose needed),
//                P  stride 68  (=4 mod 32).
// ============================================================================
#define FQ   128
#define FKV  64
#define SQW  132
#define SVW  136
#define SPW  68
#define QOFF 0
#define KOFF (FQ * SQW)                 // 16896
#define VOFF (KOFF + FKV * SQW)         // 25344
#define POFF (VOFF + FKV * SVW)         // 34048
#define FSMEM_WORDS (POFF + FQ * SPW)   // 42752
#define FSMEM_BYTES (FSMEM_WORDS * 4)   // 171008 B

__global__ __launch_bounds__(256) void flash_tf32(
    const float* __restrict__ Q, const float* __restrict__ Kg,
    const float* __restrict__ Vg, float* __restrict__ O)
{
    extern __shared__ uint32_t sm[];
    const int tid  = threadIdx.x;
    const int lane = tid & 31;
    const int w    = tid >> 5;
    const int g = lane >> 2, t = lane & 3;
    const int qt = blockIdx.x, h = blockIdx.y, b = blockIdx.z;
    const int wr = w * 16;

    const size_t qbase  = ((size_t)(b * S_ + qt * FQ)) * D_ + (size_t)h * HD_;
    const size_t kvbase = ((size_t)b * S_) * D_ + (size_t)h * HD_;

    // Load Q tile [128,128] -> smem tf32 (resident for whole kernel)
#pragma unroll
    for (int i = 0; i < 16; i++) {
        int idx = tid + i * 256;          // 0..4095 float4 slots
        int r = idx >> 5;                 // 0..127
        int c = (idx & 31) << 2;          // 0..124
        float4 v = *(const float4*)(Q + qbase + (size_t)r * D_ + c);
        *(uint4*)&sm[QOFF + r * SQW + c] = tf32x4(v);
    }

    float o[16][4];
#pragma unroll
    for (int ni = 0; ni < 16; ni++)
#pragma unroll
        for (int j = 0; j < 4; j++) o[ni][j] = 0.f;
    float m0 = -1e30f, m1 = -1e30f, l0 = 0.f, l1 = 0.f;
    const float scale = 0.08838834764831845f;   // 1/sqrt(128)

    for (int kv0 = 0; kv0 < S_; kv0 += FKV) {
        // Load K and V tiles [64,128] (V kept [kv,d] — read directly as B op)
#pragma unroll
        for (int i = 0; i < 8; i++) {
            int idx = tid + i * 256;      // 0..2047 float4 slots
            int r = idx >> 5;             // 0..63
            int c = (idx & 31) << 2;      // 0..124
            size_t goff = kvbase + (size_t)(kv0 + r) * D_ + c;
            *(uint4*)&sm[KOFF + r * SQW + c] = tf32x4(*(const float4*)(Kg + goff));
            *(uint4*)&sm[VOFF + r * SVW + c] = tf32x4(*(const float4*)(Vg + goff));
        }
        __syncthreads();

        // ---- S = Q @ K^T  (M=16 per warp, N=64, K=128) ----
        float s[8][4];
#pragma unroll
        for (int ni = 0; ni < 8; ni++)
#pragma unroll
            for (int j = 0; j < 4; j++) s[ni][j] = 0.f;

#pragma unroll
        for (int ks = 0; ks < HD_; ks += 8) {
            uint32_t af[4];
            af[0] = sm[QOFF + (wr + g    ) * SQW + ks + t    ];
            af[1] = sm[QOFF + (wr + g + 8) * SQW + ks + t    ];
            af[2] = sm[QOFF + (wr + g    ) * SQW + ks + t + 4];
            af[3] = sm[QOFF + (wr + g + 8) * SQW + ks + t + 4];
#pragma unroll
            for (int ni = 0; ni < 8; ni++) {
                uint32_t bf[2];
                bf[0] = sm[KOFF + (ni * 8 + g) * SQW + ks + t    ];
                bf[1] = sm[KOFF + (ni * 8 + g) * SQW + ks + t + 4];
                mma_tf32(s[ni], af, bf);
            }
        }

        // ---- online softmax (rows g and g+8 within the quad) ----
        float mx0 = -1e30f, mx1 = -1e30f;
#pragma unroll
        for (int ni = 0; ni < 8; ni++) {
#pragma unroll
            for (int j = 0; j < 4; j++) s[ni][j] *= scale;
            mx0 = fmaxf(mx0, fmaxf(s[ni][0], s[ni][1]));
            mx1 = fmaxf(mx1, fmaxf(s[ni][2], s[ni][3]));
        }
        mx0 = fmaxf(mx0, __shfl_xor_sync(0xffffffffu, mx0, 1));
        mx0 = fmaxf(mx0, __shfl_xor_sync(0xffffffffu, mx0, 2));
        mx1 = fmaxf(mx1, __shfl_xor_sync(0xffffffffu, mx1, 1));
        mx1 = fmaxf(mx1, __shfl_xor_sync(0xffffffffu, mx1, 2));
        float mn0 = fmaxf(m0, mx0), mn1 = fmaxf(m1, mx1);
        float a0 = __expf(m0 - mn0), a1 = __expf(m1 - mn1);
        m0 = mn0; m1 = mn1;

        float r0 = 0.f, r1 = 0.f;
#pragma unroll
        for (int ni = 0; ni < 8; ni++) {
            float p0 = __expf(s[ni][0] - mn0);
            float p1 = __expf(s[ni][1] - mn0);
            float p2 = __expf(s[ni][2] - mn1);
            float p3 = __expf(s[ni][3] - mn1);
            r0 += p0 + p1; r1 += p2 + p3;
            uint2 u01 = make_uint2(f2tf32(p0), f2tf32(p1));
            uint2 u23 = make_uint2(f2tf32(p2), f2tf32(p3));
            *(uint2*)&sm[POFF + (wr + g    ) * SPW + ni * 8 + 2 * t] = u01;
            *(uint2*)&sm[POFF + (wr + g + 8) * SPW + ni * 8 + 2 * t] = u23;
        }
        r0 += __shfl_xor_sync(0xffffffffu, r0, 1);
        r0 += __shfl_xor_sync(0xffffffffu, r0, 2);
        r1 += __shfl_xor_sync(0xffffffffu, r1, 1);
        r1 += __shfl_xor_sync(0xffffffffu, r1, 2);
        l0 = l0 * a0 + r0;
        l1 = l1 * a1 + r1;
#pragma unroll
        for (int ni = 0; ni < 16; ni++) {
            o[ni][0] *= a0; o[ni][1] *= a0; o[ni][2] *= a1; o[ni][3] *= a1;
        }
        __syncwarp();   // P stores visible to this warp's PV loads (region is warp-private)

        // ---- O += P @ V  (M=16, N=128, K=64) ----
#pragma unroll
        for (int ks = 0; ks < FKV; ks += 8) {
            uint32_t af[4];
            af[0] = sm[POFF + (wr + g    ) * SPW + ks + t    ];
            af[1] = sm[POFF + (wr + g + 8) * SPW + ks + t    ];
            af[2] = sm[POFF + (wr + g    ) * SPW + ks + t + 4];
            af[3] = sm[POFF + (wr + g + 8) * SPW + ks + t + 4];
#pragma unroll
            for (int ni = 0; ni < 16; ni++) {
                uint32_t bf[2];
                bf[0] = sm[VOFF + (ks + t    ) * SVW + ni * 8 + g];
                bf[1] = sm[VOFF + (ks + t + 4) * SVW + ni * 8 + g];
                mma_tf32(o[ni], af, bf);
            }
        }
        __syncthreads();   // protect K/V/P tiles before next iteration's overwrites
    }

    // ---- epilogue: normalize, write ctx ----
    float i0 = 1.0f / l0;
    float i1 = 1.0f / l1;
#pragma unroll
    for (int ni = 0; ni < 16; ni++) {
        int c0 = ni * 8 + 2 * t;
        *(float2*)&O[qbase + (size_t)(wr + g) * D_ + c0] =
            make_float2(o[ni][0] * i0, o[ni][1] * i0);
        *(float2*)&O[qbase + (size_t)(wr + g + 8) * D_ + c0] =
            make_float2(o[ni][2] * i1, o[ni][3] * i1);
    }
}

// ============================================================================
// Launch: q=x@wq^T, k=x@wk^T, v=x@wv^T, flash attention, out=ctx@wo^T
// ============================================================================
extern "C" void kernel_launch(void* const* d_in, const int* in_sizes, int n_in,
                              void* d_out, int out_size) {
    const float* x  = (const float*)d_in[0];
    const float* wq = (const float*)d_in[1];
    const float* wk = (const float*)d_in[2];
    const float* wv = (const float*)d_in[3];
    const float* wo = (const float*)d_in[4];
    float* out = (float*)d_out;

    float *qb, *kb, *vb, *cb;
    cudaGetSymbolAddress((void**)&qb, g_q);
    cudaGetSymbolAddress((void**)&kb, g_k);
    cudaGetSymbolAddress((void**)&vb, g_v);
    cudaGetSymbolAddress((void**)&cb, g_ctx);

    cudaFuncSetAttribute(flash_tf32,
                         cudaFuncAttributeMaxDynamicSharedMemorySize, FSMEM_BYTES);

    dim3 gg(D_ / GBN, MTOK / GBM);   // (16, 32)
    gemm_xwt_tf32<<<gg, 256>>>(x, wq, qb);
    gemm_xwt_tf32<<<gg, 256>>>(x, wk, kb);
    gemm_xwt_tf32<<<gg, 256>>>(x, wv, vb);
    flash_tf32<<<dim3(S_ / FQ, H_, B_), 256, FSMEM_BYTES>>>(qb, kb, vb, cb);
    gemm_xwt_tf32<<<gg, 256>>>(cb, wo, out);
}